// round 14
// baseline (speedup 1.0000x reference)
#include <cuda_runtime.h>
#include <cuda_bf16.h>
#include <cstdint>

#define N_NODES 100000
#define N_HEDGES 40000
#define N_INC 600000
#define D 128

#define PITCH_B 272
#define W_ROW_U16 136
#define TILE_A_BYTES (64 * PITCH_B)   // 17408

#define NB_E ((N_HEDGES + 2047) / 2048)   // 20
#define NB_V ((N_NODES + 2047) / 2048)    // 49
#define NT_E ((N_HEDGES + 63) / 64)       // 625
#define NT_V ((N_NODES + 63) / 64)        // 1563
#define HIST_BLOCKS ((N_INC + 255) / 256) // 2344
#define WSPLIT_BLOCKS ((3 * D * D + 255) / 256) // 192
#define FINAL_BLOCKS ((N_HEDGES + N_NODES + 255) / 256) // 547

#define NSM 148
#define NCTA_PLAIN (2 * NSM)   // 296
#define NCTA_FUSED NSM         // 148

// ---------------------------------------------------------------------------
// Scratch (allocation-free __device__ globals; zero-initialized at load).
// Gather outputs are stored PRE-SPLIT (bf16 hi/lo) in the exact GEMM smem
// tile layout: tile t at t*TILE_A_BYTES, row r at r*PITCH_B, dim d at 2d.
// ---------------------------------------------------------------------------
static __device__ char g_AHe[(size_t)NT_E * TILE_A_BYTES];  // norm_v hi
static __device__ char g_ALe[(size_t)NT_E * TILE_A_BYTES];  // norm_v lo
static __device__ char g_AHv[(size_t)NT_V * TILE_A_BYTES];  // norm_e hi
static __device__ char g_ALv[(size_t)NT_V * TILE_A_BYTES];  // norm_e lo
static __device__ __nv_bfloat16 g_Wh[3][D * W_ROW_U16];
static __device__ __nv_bfloat16 g_Wl[3][D * W_ROW_U16];

// CSR scratch. INVARIANT: g_cnt_* start at 0 (static zero-init); hist counts
// them up, finalize_fill resets them to 0 for the next call.
static __device__ int g_cnt_e[N_HEDGES];
static __device__ int g_cnt_v[N_NODES];
static __device__ int g_offl_e[N_HEDGES];
static __device__ int g_offl_v[N_NODES];
static __device__ int g_offF_e[N_HEDGES + 1];
static __device__ int g_offF_v[N_NODES + 1];
static __device__ int g_bsum_e[NB_E];
static __device__ int g_bsum_v[NB_V];
static __device__ int g_pos_e[N_INC];
static __device__ int g_pos_v[N_INC];
static __device__ int g_srt_e[N_INC];
static __device__ int g_srt_v[N_INC];

// ---------------------------------------------------------------------------
// Fused histogram (+position capture) + weight-split.
// ---------------------------------------------------------------------------
__global__ void hist_wsplit_kernel(const int* __restrict__ node_idx,
                                   const int* __restrict__ edge_idx,
                                   const float* __restrict__ W0,
                                   const float* __restrict__ W1,
                                   const float* __restrict__ W2) {
    int b = blockIdx.x;
    if (b < HIST_BLOCKS) {
        int i = b * 256 + threadIdx.x;
        if (i < N_INC) {
            int e = __ldg(&edge_idx[i]);
            int v = __ldg(&node_idx[i]);
            g_pos_e[i] = atomicAdd(&g_cnt_e[e], 1);
            g_pos_v[i] = atomicAdd(&g_cnt_v[v], 1);
        }
    } else {
        int i = (b - HIST_BLOCKS) * 256 + threadIdx.x;
        if (i < 3 * D * D) {
            int w = i >> 14;
            int j = i & (D * D - 1);
            const float* W = (w == 0) ? W0 : (w == 1) ? W1 : W2;
            int n = j >> 7, k = j & 127;
            float x = W[j];
            __nv_bfloat16 hi = __float2bfloat16(x);
            __nv_bfloat16 lo = __float2bfloat16(x - __bfloat162float(hi));
            g_Wh[w][n * W_ROW_U16 + k] = hi;
            g_Wl[w][n * W_ROW_U16 + k] = lo;
        }
    }
}

// ---------------------------------------------------------------------------
// Scan phase A.
// ---------------------------------------------------------------------------
__global__ void scan_phaseA2() {
    __shared__ int sm[512];
    int b = blockIdx.x;
    const int* cnt; int* off; int* bsum; int n; int lb;
    if (b < NB_E) { cnt = g_cnt_e; off = g_offl_e; bsum = g_bsum_e; n = N_HEDGES; lb = b; }
    else          { cnt = g_cnt_v; off = g_offl_v; bsum = g_bsum_v; n = N_NODES;  lb = b - NB_E; }

    int t = threadIdx.x;
    int base = lb * 2048 + t * 4;
    int v[4], s = 0;
    #pragma unroll
    for (int q = 0; q < 4; q++) {
        v[q] = (base + q < n) ? cnt[base + q] : 0;
        s += v[q];
    }
    sm[t] = s;
    __syncthreads();
    #pragma unroll
    for (int d = 1; d < 512; d <<= 1) {
        int x = (t >= d) ? sm[t - d] : 0;
        __syncthreads();
        sm[t] += x;
        __syncthreads();
    }
    int run = sm[t] - s;
    #pragma unroll
    for (int q = 0; q < 4; q++) {
        if (base + q < n) off[base + q] = run;
        run += v[q];
    }
    if (t == 511) bsum[lb] = sm[511];
}

// ---------------------------------------------------------------------------
// Fused finalize + fill.
// ---------------------------------------------------------------------------
__global__ void finalize_fill_kernel(const int* __restrict__ node_idx,
                                     const int* __restrict__ edge_idx) {
    __shared__ int pe[NB_E], pv[NB_V];
    int t = threadIdx.x;
    if (t < NB_E) pe[t] = g_bsum_e[t];
    else if (t < NB_E + NB_V) pv[t - NB_E] = g_bsum_v[t - NB_E];
    __syncthreads();
    if (t == 0) {
        int run = 0;
        #pragma unroll
        for (int i = 0; i < NB_E; i++) { int x = pe[i]; pe[i] = run; run += x; }
    } else if (t == 32) {
        int run = 0;
        #pragma unroll
        for (int i = 0; i < NB_V; i++) { int x = pv[i]; pv[i] = run; run += x; }
    }
    __syncthreads();

    int b = blockIdx.x;
    if (b < FINAL_BLOCKS) {
        int i = b * 256 + t;
        if (i < N_HEDGES) {
            g_offF_e[i] = g_offl_e[i] + pe[i >> 11];
            g_cnt_e[i] = 0;
        }
        int j = i - N_HEDGES;
        if (j >= 0 && j < N_NODES) {
            g_offF_v[j] = g_offl_v[j] + pv[j >> 11];
            g_cnt_v[j] = 0;
        }
        if (i == 0) { g_offF_e[N_HEDGES] = N_INC; g_offF_v[N_NODES] = N_INC; }
    } else {
        int i = (b - FINAL_BLOCKS) * 256 + t;
        if (i < N_INC) {
            int e = __ldg(&edge_idx[i]);
            int v = __ldg(&node_idx[i]);
            int de = __ldg(&g_offl_e[e]) + pe[e >> 11] + __ldg(&g_pos_e[i]);
            int dv = __ldg(&g_offl_v[v]) + pv[v >> 11] + __ldg(&g_pos_v[i]);
            g_srt_e[de] = v;
            g_srt_v[dv] = e;
        }
    }
}

__device__ __forceinline__ uint32_t pack_bf16x2(float x, float y) {
    __nv_bfloat16 hx = __float2bfloat16(x), hy = __float2bfloat16(y);
    return (uint32_t)__bfloat16_as_ushort(hx) | ((uint32_t)__bfloat16_as_ushort(hy) << 16);
}
__device__ __forceinline__ void split2(float x, float y, uint32_t& h, uint32_t& l) {
    h = pack_bf16x2(x, y);
    float hx = __bfloat162float(__ushort_as_bfloat16((unsigned short)(h & 0xFFFF)));
    float hy = __bfloat162float(__ushort_as_bfloat16((unsigned short)(h >> 16)));
    l = pack_bf16x2(x - hx, y - hy);
}

// ---------------------------------------------------------------------------
// Gather-reduce, HALF-WARP per destination (2 independent chains per warp),
// output written PRE-SPLIT (bf16 hi/lo) in GEMM tile layout:
//   acc[dim] = (sum_{s in seg(d)} src_w[s]*feat[s][dim]) / dst_sum[d]
// Lane (0..15) handles 8 dims: lane*8 .. lane*8+7.
// ---------------------------------------------------------------------------
__global__ void __launch_bounds__(256) gather_kernel(
    const float* __restrict__ feat, const float* __restrict__ src_w,
    const float* __restrict__ dst_sum, const int* __restrict__ off,
    const int* __restrict__ srt, int n_dst,
    char* __restrict__ outH, char* __restrict__ outL)
{
    int d = (blockIdx.x * blockDim.x + threadIdx.x) >> 4;
    if (d >= n_dst) return;
    int lane = threadIdx.x & 15;
    int jb = __ldg(&off[d]);
    int je = __ldg(&off[d + 1]);

    float4 a0 = make_float4(0.f, 0.f, 0.f, 0.f);
    float4 a1 = make_float4(0.f, 0.f, 0.f, 0.f);
    const float4* f4 = reinterpret_cast<const float4*>(feat);

    int j = jb;
    for (; j + 2 <= je; j += 2) {
        int s0 = __ldg(&srt[j]);
        int s1 = __ldg(&srt[j + 1]);
        float w0 = __ldg(&src_w[s0]);
        float w1 = __ldg(&src_w[s1]);
        float4 x0 = __ldg(f4 + (size_t)s0 * 32 + lane * 2);
        float4 x1 = __ldg(f4 + (size_t)s0 * 32 + lane * 2 + 1);
        float4 y0 = __ldg(f4 + (size_t)s1 * 32 + lane * 2);
        float4 y1 = __ldg(f4 + (size_t)s1 * 32 + lane * 2 + 1);
        a0.x += w0 * x0.x + w1 * y0.x;
        a0.y += w0 * x0.y + w1 * y0.y;
        a0.z += w0 * x0.z + w1 * y0.z;
        a0.w += w0 * x0.w + w1 * y0.w;
        a1.x += w0 * x1.x + w1 * y1.x;
        a1.y += w0 * x1.y + w1 * y1.y;
        a1.z += w0 * x1.z + w1 * y1.z;
        a1.w += w0 * x1.w + w1 * y1.w;
    }
    if (j < je) {
        int s0 = __ldg(&srt[j]);
        float w0 = __ldg(&src_w[s0]);
        float4 x0 = __ldg(f4 + (size_t)s0 * 32 + lane * 2);
        float4 x1 = __ldg(f4 + (size_t)s0 * 32 + lane * 2 + 1);
        a0.x += w0 * x0.x; a0.y += w0 * x0.y; a0.z += w0 * x0.z; a0.w += w0 * x0.w;
        a1.x += w0 * x1.x; a1.y += w0 * x1.y; a1.z += w0 * x1.z; a1.w += w0 * x1.w;
    }

    float rinv = 1.0f / __ldg(&dst_sum[d]);
    a0.x *= rinv; a0.y *= rinv; a0.z *= rinv; a0.w *= rinv;
    a1.x *= rinv; a1.y *= rinv; a1.z *= rinv; a1.w *= rinv;

    uint4 h, l;
    split2(a0.x, a0.y, h.x, l.x);
    split2(a0.z, a0.w, h.y, l.y);
    split2(a1.x, a1.y, h.z, l.z);
    split2(a1.z, a1.w, h.w, l.w);

    size_t base = (size_t)(d >> 6) * TILE_A_BYTES + (d & 63) * PITCH_B + lane * 16;
    *reinterpret_cast<uint4*>(outH + base) = h;
    *reinterpret_cast<uint4*>(outL + base) = l;
}

// ---------------------------------------------------------------------------
// PTX helpers
// ---------------------------------------------------------------------------
__device__ __forceinline__ uint32_t smem_u32(const void* p) {
    uint32_t a;
    asm("{ .reg .u64 t; cvta.to.shared.u64 t, %1; cvt.u32.u64 %0, t; }"
        : "=r"(a) : "l"(p));
    return a;
}
__device__ __forceinline__ void ldm_x4(uint32_t* r, uint32_t addr) {
    asm volatile("ldmatrix.sync.aligned.m8n8.x4.shared.b16 {%0,%1,%2,%3}, [%4];"
                 : "=r"(r[0]), "=r"(r[1]), "=r"(r[2]), "=r"(r[3]) : "r"(addr));
}
__device__ __forceinline__ void mma_bf16(float* c, const uint32_t* a,
                                         uint32_t b0, uint32_t b1) {
    asm volatile("mma.sync.aligned.m16n8k16.row.col.f32.bf16.bf16.f32 "
                 "{%0,%1,%2,%3},{%4,%5,%6,%7},{%8,%9},{%0,%1,%2,%3};"
                 : "+f"(c[0]), "+f"(c[1]), "+f"(c[2]), "+f"(c[3])
                 : "r"(a[0]), "r"(a[1]), "r"(a[2]), "r"(a[3]), "r"(b0), "r"(b1));
}
__device__ __forceinline__ void cp_async16(uint32_t saddr, const void* g) {
    asm volatile("cp.async.ca.shared.global [%0], [%1], 16;"
                 :: "r"(saddr), "l"(g) : "memory");
}
#define CP_COMMIT() asm volatile("cp.async.commit_group;" ::: "memory")
#define CP_WAIT0()  asm volatile("cp.async.wait_group 0;" ::: "memory")

// smem layout
#define SM_AHI 0
#define SM_ALO (SM_AHI + 64 * PITCH_B)        // 17408
#define SM_W0H (SM_ALO + 64 * PITCH_B)        // 34816
#define SM_W0L (SM_W0H + 128 * PITCH_B)       // 69632
#define SM_TOT_P (SM_W0L + 128 * PITCH_B)     // 104448 (plain)
#define SM_W1H SM_TOT_P                        // 104448
#define SM_W1L (SM_W1H + 128 * PITCH_B)       // 139264
#define SM_TOT_F (SM_W1L + 128 * PITCH_B)     // 174080 (fused)

// ---- per-tile building blocks --------------------------------------------
// Raw pre-split A prefetch into regs (8 uint4).
#define LOAD_A_SPLIT(vh, vl, AH, AL, tile)                                     \
    {                                                                          \
        if ((tile) < ntiles) {                                                 \
            size_t bo = (size_t)(tile) * TILE_A_BYTES                          \
                        + (tid >> 2) * PITCH_B + (tid & 3) * 64;               \
            const uint4* ph = reinterpret_cast<const uint4*>((AH) + bo);       \
            const uint4* pl = reinterpret_cast<const uint4*>((AL) + bo);       \
            _Pragma("unroll")                                                  \
            for (int q = 0; q < 4; q++) { vh[q] = __ldg(ph + q); vl[q] = __ldg(pl + q); } \
        }                                                                      \
    }

#define STORE_A_SPLIT(vh, vl)                                                  \
    {                                                                          \
        char* dh = smem + SM_AHI + (tid >> 2) * PITCH_B + (tid & 3) * 64;      \
        char* dl = smem + SM_ALO + (tid >> 2) * PITCH_B + (tid & 3) * 64;      \
        _Pragma("unroll")                                                      \
        for (int q = 0; q < 4; q++) {                                          \
            reinterpret_cast<uint4*>(dh)[q] = vh[q];                           \
            reinterpret_cast<uint4*>(dl)[q] = vl[q];                           \
        }                                                                      \
    }

// Dense f32 A load + convert (efeat phase only).
#define LOAD_A_REGS(v, Aptr, tile)                                             \
    {                                                                          \
        int gm = (tile) * 64 + (tid >> 2);                                     \
        if ((tile) < ntiles && gm < M) {                                       \
            const float4* ap = reinterpret_cast<const float4*>(Aptr)           \
                               + (size_t)gm * 32 + (tid & 3) * 8;              \
            _Pragma("unroll")                                                  \
            for (int q = 0; q < 8; q++) {                                      \
                float4 f = __ldg(ap + q);                                      \
                v[4 * q] = f.x; v[4 * q + 1] = f.y;                            \
                v[4 * q + 2] = f.z; v[4 * q + 3] = f.w;                        \
            }                                                                  \
        } else {                                                               \
            _Pragma("unroll")                                                  \
            for (int q = 0; q < 32; q++) v[q] = 0.f;                           \
        }                                                                      \
    }

#define STORE_CONVERT(v)                                                       \
    {                                                                          \
        uint32_t hp[16], lp[16];                                               \
        _Pragma("unroll")                                                      \
        for (int q = 0; q < 16; q++) split2(v[2 * q], v[2 * q + 1], hp[q], lp[q]); \
        char* dst_h = smem + SM_AHI + (tid >> 2) * PITCH_B + (tid & 3) * 64;   \
        char* dst_l = smem + SM_ALO + (tid >> 2) * PITCH_B + (tid & 3) * 64;   \
        _Pragma("unroll")                                                      \
        for (int q = 0; q < 4; q++) {                                          \
            *reinterpret_cast<uint4*>(dst_h + 16 * q) =                        \
                make_uint4(hp[4 * q], hp[4 * q + 1], hp[4 * q + 2], hp[4 * q + 3]); \
            *reinterpret_cast<uint4*>(dst_l + 16 * q) =                        \
                make_uint4(lp[4 * q], lp[4 * q + 1], lp[4 * q + 2], lp[4 * q + 3]); \
        }                                                                      \
    }

#define ZERO_C()                                                               \
    _Pragma("unroll")                                                          \
    for (int mf = 0; mf < 2; mf++)                                             \
        _Pragma("unroll")                                                      \
        for (int nt = 0; nt < 4; nt++)                                         \
            _Pragma("unroll")                                                  \
            for (int i = 0; i < 4; i++) c[mf][nt][i] = 0.f;

#define MAINLOOP(WHB, WLB)                                                     \
    _Pragma("unroll")                                                          \
    for (int kt = 0; kt < 8; kt++) {                                           \
        const uint32_t kb = kt * 32;                                           \
        uint32_t ah[2][4], al[2][4];                                           \
        ldm_x4(ah[0], sb + SM_AHI + aoff + kb);                                \
        ldm_x4(ah[1], sb + SM_AHI + aoff + 16 * PITCH_B + kb);                 \
        ldm_x4(al[0], sb + SM_ALO + aoff + kb);                                \
        ldm_x4(al[1], sb + SM_ALO + aoff + 16 * PITCH_B + kb);                 \
        uint32_t bh[8], bl[8];                                                 \
        ldm_x4(&bh[0], sb + (WHB) + boff + kb);                                \
        ldm_x4(&bh[4], sb + (WHB) + boff + 16 * PITCH_B + kb);                 \
        ldm_x4(&bl[0], sb + (WLB) + boff + kb);                                \
        ldm_x4(&bl[4], sb + (WLB) + boff + 16 * PITCH_B + kb);                 \
        _Pragma("unroll")                                                      \
        for (int nt = 0; nt < 4; nt++) {                                       \
            uint32_t b0h = bh[2 * nt], b1h = bh[2 * nt + 1];                   \
            uint32_t b0l = bl[2 * nt], b1l = bl[2 * nt + 1];                   \
            _Pragma("unroll")                                                  \
            for (int mf = 0; mf < 2; mf++) {                                   \
                mma_bf16(c[mf][nt], ah[mf], b0h, b1h);                         \
                mma_bf16(c[mf][nt], al[mf], b0h, b1h);                         \
                mma_bf16(c[mf][nt], ah[mf], b0l, b1l);                         \
            }                                                                  \
        }                                                                      \
    }

#define STAGE_W(WHB, WLB, whg, wlg)                                            \
    _Pragma("unroll")                                                          \
    for (int i = tid; i < 2176; i += 256) {                                    \
        cp_async16(sb + (WHB) + i * 16, (const char*)(whg) + i * 16);          \
        cp_async16(sb + (WLB) + i * 16, (const char*)(wlg) + i * 16);          \
    }

// ---------------------------------------------------------------------------
// Persistent plain GEMM, pre-split A: Out = relu(A @ W^T + bias).
// ---------------------------------------------------------------------------
__global__ void __launch_bounds__(256) gemm_plain_kernel(
    const char* __restrict__ AH, const char* __restrict__ AL,
    const float* __restrict__ bias0,
    const __nv_bfloat16* __restrict__ Wh0, const __nv_bfloat16* __restrict__ Wl0,
    int M, float* __restrict__ Out)
{
    extern __shared__ char smem[];
    const uint32_t sb = smem_u32(smem);
    const int tid = threadIdx.x;
    const int lane = tid & 31;
    const int warp = tid >> 5;
    const int wm = warp & 1;
    const int wn = warp >> 1;
    const int ntiles = (M + 63) / 64;

    const int rA = (lane & 7) + ((lane >> 3) & 1) * 8;
    const int kA = ((lane >> 4) & 1) * 8;
    const int rB = (lane & 7) + ((lane >> 4) & 1) * 8;
    const int kB = ((lane >> 3) & 1) * 8;
    const uint32_t aoff = (uint32_t)((wm * 32 + rA) * PITCH_B + kA * 2);
    const uint32_t boff = (uint32_t)((wn * 32 + rB) * PITCH_B + kB * 2);

    STAGE_W(SM_W0H, SM_W0L, Wh0, Wl0);
    CP_COMMIT();

    uint4 vh[4], vl[4];
    LOAD_A_SPLIT(vh, vl, AH, AL, (int)blockIdx.x);
    CP_WAIT0();

    for (int t = blockIdx.x; t < ntiles; t += gridDim.x) {
        __syncthreads();
        STORE_A_SPLIT(vh, vl);
        __syncthreads();
        LOAD_A_SPLIT(vh, vl, AH, AL, t + (int)gridDim.x);   // prefetch next tile

        float c[2][4][4];
        ZERO_C();
        MAINLOOP(SM_W0H, SM_W0L);

        const int m_base = t * 64;
        #pragma unroll
        for (int nt = 0; nt < 4; nt++) {
            int col = wn * 32 + nt * 8 + 2 * (lane & 3);
            float2 b = __ldg(reinterpret_cast<const float2*>(&bias0[col]));
            #pragma unroll
            for (int mf = 0; mf < 2; mf++) {
                int row0 = m_base + wm * 32 + mf * 16 + (lane >> 2);
                float2 o01 = make_float2(fmaxf(c[mf][nt][0] + b.x, 0.f),
                                         fmaxf(c[mf][nt][1] + b.y, 0.f));
                float2 o23 = make_float2(fmaxf(c[mf][nt][2] + b.x, 0.f),
                                         fmaxf(c[mf][nt][3] + b.y, 0.f));
                if (row0 < M)
                    *reinterpret_cast<float2*>(&Out[(size_t)row0 * D + col]) = o01;
                if (row0 + 8 < M)
                    *reinterpret_cast<float2*>(&Out[(size_t)(row0 + 8) * D + col]) = o23;
            }
        }
    }
}

// ---------------------------------------------------------------------------
// Persistent fused GEMM: Out = relu(A0@W0^T + b0) + A1@W1^T + b1.
// Phase 0: pre-split A (gather output). Phase 1: dense f32 efeat (convert).
// ---------------------------------------------------------------------------
__global__ void __launch_bounds__(256) gemm_fused_kernel(
    const char* __restrict__ AH, const char* __restrict__ AL,
    const float* __restrict__ bias0,
    const __nv_bfloat16* __restrict__ Wh0, const __nv_bfloat16* __restrict__ Wl0,
    const float* __restrict__ A1, const float* __restrict__ bias1,
    const __nv_bfloat16* __restrict__ Wh1, const __nv_bfloat16* __restrict__ Wl1,
    int M, float* __restrict__ Out)
{
    extern __shared__ char smem[];
    const uint32_t sb = smem_u32(smem);
    const int tid = threadIdx.x;
    const int lane = tid & 31;
    const int warp = tid >> 5;
    const int wm = warp & 1;
    const int wn = warp >> 1;
    const int ntiles = (M + 63) / 64;

    const int rA = (lane & 7) + ((lane >> 3) & 1) * 8;
    const int kA = ((lane >> 4) & 1) * 8;
    const int rB = (lane & 7) + ((lane >> 4) & 1) * 8;
    const int kB = ((lane >> 3) & 1) * 8;
    const uint32_t aoff = (uint32_t)((wm * 32 + rA) * PITCH_B + kA * 2);
    const uint32_t boff = (uint32_t)((wn * 32 + rB) * PITCH_B + kB * 2);

    STAGE_W(SM_W0H, SM_W0L, Wh0, Wl0);
    STAGE_W(SM_W1H, SM_W1L, Wh1, Wl1);
    CP_COMMIT();

    uint4 vh[4], vl[4];
    float v1[32];
    LOAD_A_SPLIT(vh, vl, AH, AL, (int)blockIdx.x);
    CP_WAIT0();

    for (int t = blockIdx.x; t < ntiles; t += gridDim.x) {
        __syncthreads();
        STORE_A_SPLIT(vh, vl);
        __syncthreads();
        LOAD_A_REGS(v1, A1, t);             // phase-1 A prefetch under mainloop0

        float c[2][4][4];
        ZERO_C();
        MAINLOOP(SM_W0H, SM_W0L);

        // mid-fusion: relu(C + bias0)
        #pragma unroll
        for (int nt = 0; nt < 4; nt++) {
            int col = wn * 32 + nt * 8 + 2 * (lane & 3);
            float2 b = __ldg(reinterpret_cast<const float2*>(&bias0[col]));
            #pragma unroll
            for (int mf = 0; mf < 2; mf++) {
                c[mf][nt][0] = fmaxf(c[mf][nt][0] + b.x, 0.f);
                c[mf][nt][1] = fmaxf(c[mf][nt][1] + b.y, 0.f);
                c[mf][nt][2] = fmaxf(c[mf][nt][2] + b.x, 0.f);
                c[mf][nt][3] = fmaxf(c[mf][nt][3] + b.y, 0.f);
            }
        }

        __syncthreads();
        STORE_CONVERT(v1);
        __syncthreads();
        LOAD_A_SPLIT(vh, vl, AH, AL, t + (int)gridDim.x);  // next-tile prefetch

        MAINLOOP(SM_W1H, SM_W1L);

        const int m_base = t * 64;
        #pragma unroll
        for (int nt = 0; nt < 4; nt++) {
            int col = wn * 32 + nt * 8 + 2 * (lane & 3);
            float2 b = __ldg(reinterpret_cast<const float2*>(&bias1[col]));
            #pragma unroll
            for (int mf = 0; mf < 2; mf++) {
                int row0 = m_base + wm * 32 + mf * 16 + (lane >> 2);
                float2 o01 = make_float2(c[mf][nt][0] + b.x, c[mf][nt][1] + b.y);
                float2 o23 = make_float2(c[mf][nt][2] + b.x, c[mf][nt][3] + b.y);
                if (row0 < M)
                    *reinterpret_cast<float2*>(&Out[(size_t)row0 * D + col]) = o01;
                if (row0 + 8 < M)
                    *reinterpret_cast<float2*>(&Out[(size_t)(row0 + 8) * D + col]) = o23;
            }
        }
    }
}

extern "C" void kernel_launch(void* const* d_in, const int* in_sizes, int n_in,
                              void* d_out, int out_size) {
    (void)in_sizes; (void)n_in; (void)out_size;

    const float* vfeat = (const float*)d_in[0];
    const float* efeat = (const float*)d_in[1];
    const float* v_reg_weight = (const float*)d_in[2];
    const float* v_reg_sum    = (const float*)d_in[3];
    const float* e_reg_weight = (const float*)d_in[4];
    const float* e_reg_sum    = (const float*)d_in[5];
    const float* W_ve = (const float*)d_in[6];
    const float* b_ve = (const float*)d_in[7];
    const float* W_ev = (const float*)d_in[8];
    const float* b_ev = (const float*)d_in[9];
    const float* W_ef = (const float*)d_in[10];
    const float* b_ef = (const float*)d_in[11];
    const int* node_idx = (const int*)d_in[12];
    const int* edge_idx = (const int*)d_in[13];

    float* out = (float*)d_out;
    float* vfeat_out = out;
    float* efeat_out = out + (size_t)N_NODES * D;

    __nv_bfloat16 *wh_ptr, *wl_ptr;
    int *offF_e_ptr, *offF_v_ptr, *srt_e_ptr, *srt_v_ptr;
    char *ahe, *ale, *ahv, *alv;
    cudaGetSymbolAddress((void**)&wh_ptr, g_Wh);
    cudaGetSymbolAddress((void**)&wl_ptr, g_Wl);
    cudaGetSymbolAddress((void**)&offF_e_ptr, g_offF_e);
    cudaGetSymbolAddress((void**)&offF_v_ptr, g_offF_v);
    cudaGetSymbolAddress((void**)&srt_e_ptr, g_srt_e);
    cudaGetSymbolAddress((void**)&srt_v_ptr, g_srt_v);
    cudaGetSymbolAddress((void**)&ahe, g_AHe);
    cudaGetSymbolAddress((void**)&ale, g_ALe);
    cudaGetSymbolAddress((void**)&ahv, g_AHv);
    cudaGetSymbolAddress((void**)&alv, g_ALv);

    cudaFuncSetAttribute(gemm_fused_kernel,
                         cudaFuncAttributeMaxDynamicSharedMemorySize, SM_TOT_F);
    cudaFuncSetAttribute(gemm_plain_kernel,
                         cudaFuncAttributeMaxDynamicSharedMemorySize, SM_TOT_P);

    const size_t WSZ = (size_t)D * W_ROW_U16;

    // --- CSR build + weight split (3 launches) ---
    hist_wsplit_kernel<<<HIST_BLOCKS + WSPLIT_BLOCKS, 256>>>(
        node_idx, edge_idx, W_ve, W_ef, W_ev);
    scan_phaseA2<<<NB_E + NB_V, 512>>>();
    finalize_fill_kernel<<<FINAL_BLOCKS + HIST_BLOCKS, 256>>>(node_idx, edge_idx);

    // --- g1: gather nodes -> edges (pre-split output) ---
    gather_kernel<<<(N_HEDGES * 16 + 255) / 256, 256>>>(
        vfeat, v_reg_weight, e_reg_sum, offF_e_ptr, srt_e_ptr, N_HEDGES, ahe, ale);

    // efeat_out = relu(norm_v @ W_ve^T + b_ve) + efeat @ W_ef^T + b_ef
    gemm_fused_kernel<<<NCTA_FUSED, 256, SM_TOT_F>>>(
        ahe, ale, b_ve, wh_ptr + 0 * WSZ, wl_ptr + 0 * WSZ,
        efeat, b_ef, wh_ptr + 1 * WSZ, wl_ptr + 1 * WSZ,
        N_HEDGES, efeat_out);

    // --- g2: gather edges -> nodes (pre-split output) ---
    gather_kernel<<<(N_NODES * 16 + 255) / 256, 256>>>(
        efeat_out, e_reg_weight, v_reg_sum, offF_v_ptr, srt_v_ptr, N_NODES, ahv, alv);

    // vfeat_out = relu(norm_e @ W_ev^T + b_ev)
    gemm_plain_kernel<<<NCTA_PLAIN, 256, SM_TOT_P>>>(
        ahv, alv, b_ev, wh_ptr + 2 * WSZ, wl_ptr + 2 * WSZ,
        N_NODES, vfeat_out);
}

// round 15
// speedup vs baseline: 1.0712x; 1.0712x over previous
#include <cuda_runtime.h>
#include <cuda_bf16.h>
#include <cstdint>

#define N_NODES 100000
#define N_HEDGES 40000
#define N_INC 600000
#define D 128

#define PITCH_B 272
#define W_ROW_U16 136
#define TILE_A_BYTES (64 * PITCH_B)   // 17408

#define NB_E ((N_HEDGES + 2047) / 2048)   // 20
#define NB_V ((N_NODES + 2047) / 2048)    // 49
#define NT_E ((N_HEDGES + 63) / 64)       // 625
#define HIST_BLOCKS ((N_INC + 255) / 256) // 2344
#define WSPLIT_BLOCKS ((3 * D * D + 255) / 256) // 192
#define FINAL_BLOCKS ((N_HEDGES + N_NODES + 255) / 256) // 547

#define NSM 148
#define NCTA_PLAIN (2 * NSM)   // 296
#define NCTA_FUSED NSM         // 148

// ---------------------------------------------------------------------------
// Scratch (allocation-free __device__ globals; zero-initialized at load).
// ---------------------------------------------------------------------------
static __device__ char g_AHe[(size_t)NT_E * TILE_A_BYTES];  // g1 output, bf16 hi
static __device__ char g_ALe[(size_t)NT_E * TILE_A_BYTES];  // g1 output, bf16 lo
static __device__ float g_Y[(size_t)N_HEDGES * D];          // efeat_out @ W_ev^T
static __device__ __nv_bfloat16 g_Wh[3][D * W_ROW_U16];
static __device__ __nv_bfloat16 g_Wl[3][D * W_ROW_U16];

// CSR scratch. INVARIANT: g_cnt_* start at 0 (static zero-init); hist counts
// them up, finalize_fill resets them to 0 for the next call.
static __device__ int g_cnt_e[N_HEDGES];
static __device__ int g_cnt_v[N_NODES];
static __device__ int g_offl_e[N_HEDGES];
static __device__ int g_offl_v[N_NODES];
static __device__ int g_offF_e[N_HEDGES + 1];
static __device__ int g_offF_v[N_NODES + 1];
static __device__ int g_bsum_e[NB_E];
static __device__ int g_bsum_v[NB_V];
static __device__ int g_pos_e[N_INC];
static __device__ int g_pos_v[N_INC];
static __device__ int g_srt_e[N_INC];
static __device__ int g_srt_v[N_INC];

// ---------------------------------------------------------------------------
// Fused histogram (+position capture) + weight-split.
// ---------------------------------------------------------------------------
__global__ void hist_wsplit_kernel(const int* __restrict__ node_idx,
                                   const int* __restrict__ edge_idx,
                                   const float* __restrict__ W0,
                                   const float* __restrict__ W1,
                                   const float* __restrict__ W2) {
    int b = blockIdx.x;
    if (b < HIST_BLOCKS) {
        int i = b * 256 + threadIdx.x;
        if (i < N_INC) {
            int e = __ldg(&edge_idx[i]);
            int v = __ldg(&node_idx[i]);
            g_pos_e[i] = atomicAdd(&g_cnt_e[e], 1);
            g_pos_v[i] = atomicAdd(&g_cnt_v[v], 1);
        }
    } else {
        int i = (b - HIST_BLOCKS) * 256 + threadIdx.x;
        if (i < 3 * D * D) {
            int w = i >> 14;
            int j = i & (D * D - 1);
            const float* W = (w == 0) ? W0 : (w == 1) ? W1 : W2;
            int n = j >> 7, k = j & 127;
            float x = W[j];
            __nv_bfloat16 hi = __float2bfloat16(x);
            __nv_bfloat16 lo = __float2bfloat16(x - __bfloat162float(hi));
            g_Wh[w][n * W_ROW_U16 + k] = hi;
            g_Wl[w][n * W_ROW_U16 + k] = lo;
        }
    }
}

// ---------------------------------------------------------------------------
// Scan phase A.
// ---------------------------------------------------------------------------
__global__ void scan_phaseA2() {
    __shared__ int sm[512];
    int b = blockIdx.x;
    const int* cnt; int* off; int* bsum; int n; int lb;
    if (b < NB_E) { cnt = g_cnt_e; off = g_offl_e; bsum = g_bsum_e; n = N_HEDGES; lb = b; }
    else          { cnt = g_cnt_v; off = g_offl_v; bsum = g_bsum_v; n = N_NODES;  lb = b - NB_E; }

    int t = threadIdx.x;
    int base = lb * 2048 + t * 4;
    int v[4], s = 0;
    #pragma unroll
    for (int q = 0; q < 4; q++) {
        v[q] = (base + q < n) ? cnt[base + q] : 0;
        s += v[q];
    }
    sm[t] = s;
    __syncthreads();
    #pragma unroll
    for (int d = 1; d < 512; d <<= 1) {
        int x = (t >= d) ? sm[t - d] : 0;
        __syncthreads();
        sm[t] += x;
        __syncthreads();
    }
    int run = sm[t] - s;
    #pragma unroll
    for (int q = 0; q < 4; q++) {
        if (base + q < n) off[base + q] = run;
        run += v[q];
    }
    if (t == 511) bsum[lb] = sm[511];
}

// ---------------------------------------------------------------------------
// Fused finalize + fill.
// ---------------------------------------------------------------------------
__global__ void finalize_fill_kernel(const int* __restrict__ node_idx,
                                     const int* __restrict__ edge_idx) {
    __shared__ int pe[NB_E], pv[NB_V];
    int t = threadIdx.x;
    if (t < NB_E) pe[t] = g_bsum_e[t];
    else if (t < NB_E + NB_V) pv[t - NB_E] = g_bsum_v[t - NB_E];
    __syncthreads();
    if (t == 0) {
        int run = 0;
        #pragma unroll
        for (int i = 0; i < NB_E; i++) { int x = pe[i]; pe[i] = run; run += x; }
    } else if (t == 32) {
        int run = 0;
        #pragma unroll
        for (int i = 0; i < NB_V; i++) { int x = pv[i]; pv[i] = run; run += x; }
    }
    __syncthreads();

    int b = blockIdx.x;
    if (b < FINAL_BLOCKS) {
        int i = b * 256 + t;
        if (i < N_HEDGES) {
            g_offF_e[i] = g_offl_e[i] + pe[i >> 11];
            g_cnt_e[i] = 0;
        }
        int j = i - N_HEDGES;
        if (j >= 0 && j < N_NODES) {
            g_offF_v[j] = g_offl_v[j] + pv[j >> 11];
            g_cnt_v[j] = 0;
        }
        if (i == 0) { g_offF_e[N_HEDGES] = N_INC; g_offF_v[N_NODES] = N_INC; }
    } else {
        int i = (b - FINAL_BLOCKS) * 256 + t;
        if (i < N_INC) {
            int e = __ldg(&edge_idx[i]);
            int v = __ldg(&node_idx[i]);
            int de = __ldg(&g_offl_e[e]) + pe[e >> 11] + __ldg(&g_pos_e[i]);
            int dv = __ldg(&g_offl_v[v]) + pv[v >> 11] + __ldg(&g_pos_v[i]);
            g_srt_e[de] = v;
            g_srt_v[dv] = e;
        }
    }
}

__device__ __forceinline__ uint32_t pack_bf16x2(float x, float y) {
    __nv_bfloat16 hx = __float2bfloat16(x), hy = __float2bfloat16(y);
    return (uint32_t)__bfloat16_as_ushort(hx) | ((uint32_t)__bfloat16_as_ushort(hy) << 16);
}
__device__ __forceinline__ void split2(float x, float y, uint32_t& h, uint32_t& l) {
    h = pack_bf16x2(x, y);
    float hx = __bfloat162float(__ushort_as_bfloat16((unsigned short)(h & 0xFFFF)));
    float hy = __bfloat162float(__ushort_as_bfloat16((unsigned short)(h >> 16)));
    l = pack_bf16x2(x - hx, y - hy);
}

// ---------------------------------------------------------------------------
// g1 gather-reduce, HALF-WARP per destination, output PRE-SPLIT bf16 hi/lo
// in GEMM tile layout. Lane (0..15) handles 8 dims.
// ---------------------------------------------------------------------------
__global__ void __launch_bounds__(256) gather_kernel(
    const float* __restrict__ feat, const float* __restrict__ src_w,
    const float* __restrict__ dst_sum, const int* __restrict__ off,
    const int* __restrict__ srt, int n_dst,
    char* __restrict__ outH, char* __restrict__ outL)
{
    int d = (blockIdx.x * blockDim.x + threadIdx.x) >> 4;
    if (d >= n_dst) return;
    int lane = threadIdx.x & 15;
    int jb = __ldg(&off[d]);
    int je = __ldg(&off[d + 1]);

    float4 a0 = make_float4(0.f, 0.f, 0.f, 0.f);
    float4 a1 = make_float4(0.f, 0.f, 0.f, 0.f);
    const float4* f4 = reinterpret_cast<const float4*>(feat);

    int j = jb;
    for (; j + 2 <= je; j += 2) {
        int s0 = __ldg(&srt[j]);
        int s1 = __ldg(&srt[j + 1]);
        float w0 = __ldg(&src_w[s0]);
        float w1 = __ldg(&src_w[s1]);
        float4 x0 = __ldg(f4 + (size_t)s0 * 32 + lane * 2);
        float4 x1 = __ldg(f4 + (size_t)s0 * 32 + lane * 2 + 1);
        float4 y0 = __ldg(f4 + (size_t)s1 * 32 + lane * 2);
        float4 y1 = __ldg(f4 + (size_t)s1 * 32 + lane * 2 + 1);
        a0.x += w0 * x0.x + w1 * y0.x;
        a0.y += w0 * x0.y + w1 * y0.y;
        a0.z += w0 * x0.z + w1 * y0.z;
        a0.w += w0 * x0.w + w1 * y0.w;
        a1.x += w0 * x1.x + w1 * y1.x;
        a1.y += w0 * x1.y + w1 * y1.y;
        a1.z += w0 * x1.z + w1 * y1.z;
        a1.w += w0 * x1.w + w1 * y1.w;
    }
    if (j < je) {
        int s0 = __ldg(&srt[j]);
        float w0 = __ldg(&src_w[s0]);
        float4 x0 = __ldg(f4 + (size_t)s0 * 32 + lane * 2);
        float4 x1 = __ldg(f4 + (size_t)s0 * 32 + lane * 2 + 1);
        a0.x += w0 * x0.x; a0.y += w0 * x0.y; a0.z += w0 * x0.z; a0.w += w0 * x0.w;
        a1.x += w0 * x1.x; a1.y += w0 * x1.y; a1.z += w0 * x1.z; a1.w += w0 * x1.w;
    }

    float rinv = 1.0f / __ldg(&dst_sum[d]);
    a0.x *= rinv; a0.y *= rinv; a0.z *= rinv; a0.w *= rinv;
    a1.x *= rinv; a1.y *= rinv; a1.z *= rinv; a1.w *= rinv;

    uint4 h, l;
    split2(a0.x, a0.y, h.x, l.x);
    split2(a0.z, a0.w, h.y, l.y);
    split2(a1.x, a1.y, h.z, l.z);
    split2(a1.z, a1.w, h.w, l.w);

    size_t base = (size_t)(d >> 6) * TILE_A_BYTES + (d & 63) * PITCH_B + lane * 16;
    *reinterpret_cast<uint4*>(outH + base) = h;
    *reinterpret_cast<uint4*>(outL + base) = l;
}

// ---------------------------------------------------------------------------
// Final gather (stage 2, commuted): vfeat_out[d] = relu(gather(Y)/vsum + bias)
// Half-warp per destination; lane handles 8 dims; writes final f32 output.
// ---------------------------------------------------------------------------
__global__ void __launch_bounds__(256) gather_final_kernel(
    const float* __restrict__ Y, const float* __restrict__ src_w,
    const float* __restrict__ dst_sum, const int* __restrict__ off,
    const int* __restrict__ srt, int n_dst,
    const float* __restrict__ bias, float* __restrict__ out)
{
    int d = (blockIdx.x * blockDim.x + threadIdx.x) >> 4;
    if (d >= n_dst) return;
    int lane = threadIdx.x & 15;
    int jb = __ldg(&off[d]);
    int je = __ldg(&off[d + 1]);

    float4 a0 = make_float4(0.f, 0.f, 0.f, 0.f);
    float4 a1 = make_float4(0.f, 0.f, 0.f, 0.f);
    const float4* f4 = reinterpret_cast<const float4*>(Y);

    int j = jb;
    for (; j + 2 <= je; j += 2) {
        int s0 = __ldg(&srt[j]);
        int s1 = __ldg(&srt[j + 1]);
        float w0 = __ldg(&src_w[s0]);
        float w1 = __ldg(&src_w[s1]);
        float4 x0 = __ldg(f4 + (size_t)s0 * 32 + lane * 2);
        float4 x1 = __ldg(f4 + (size_t)s0 * 32 + lane * 2 + 1);
        float4 y0 = __ldg(f4 + (size_t)s1 * 32 + lane * 2);
        float4 y1 = __ldg(f4 + (size_t)s1 * 32 + lane * 2 + 1);
        a0.x += w0 * x0.x + w1 * y0.x;
        a0.y += w0 * x0.y + w1 * y0.y;
        a0.z += w0 * x0.z + w1 * y0.z;
        a0.w += w0 * x0.w + w1 * y0.w;
        a1.x += w0 * x1.x + w1 * y1.x;
        a1.y += w0 * x1.y + w1 * y1.y;
        a1.z += w0 * x1.z + w1 * y1.z;
        a1.w += w0 * x1.w + w1 * y1.w;
    }
    if (j < je) {
        int s0 = __ldg(&srt[j]);
        float w0 = __ldg(&src_w[s0]);
        float4 x0 = __ldg(f4 + (size_t)s0 * 32 + lane * 2);
        float4 x1 = __ldg(f4 + (size_t)s0 * 32 + lane * 2 + 1);
        a0.x += w0 * x0.x; a0.y += w0 * x0.y; a0.z += w0 * x0.z; a0.w += w0 * x0.w;
        a1.x += w0 * x1.x; a1.y += w0 * x1.y; a1.z += w0 * x1.z; a1.w += w0 * x1.w;
    }

    float rinv = 1.0f / __ldg(&dst_sum[d]);
    float4 b0 = __ldg(reinterpret_cast<const float4*>(bias) + lane * 2);
    float4 b1 = __ldg(reinterpret_cast<const float4*>(bias) + lane * 2 + 1);
    float4 o0, o1;
    o0.x = fmaxf(a0.x * rinv + b0.x, 0.f);
    o0.y = fmaxf(a0.y * rinv + b0.y, 0.f);
    o0.z = fmaxf(a0.z * rinv + b0.z, 0.f);
    o0.w = fmaxf(a0.w * rinv + b0.w, 0.f);
    o1.x = fmaxf(a1.x * rinv + b1.x, 0.f);
    o1.y = fmaxf(a1.y * rinv + b1.y, 0.f);
    o1.z = fmaxf(a1.z * rinv + b1.z, 0.f);
    o1.w = fmaxf(a1.w * rinv + b1.w, 0.f);

    float4* po = reinterpret_cast<float4*>(out) + (size_t)d * 32 + lane * 2;
    po[0] = o0;
    po[1] = o1;
}

// ---------------------------------------------------------------------------
// PTX helpers
// ---------------------------------------------------------------------------
__device__ __forceinline__ uint32_t smem_u32(const void* p) {
    uint32_t a;
    asm("{ .reg .u64 t; cvta.to.shared.u64 t, %1; cvt.u32.u64 %0, t; }"
        : "=r"(a) : "l"(p));
    return a;
}
__device__ __forceinline__ void ldm_x4(uint32_t* r, uint32_t addr) {
    asm volatile("ldmatrix.sync.aligned.m8n8.x4.shared.b16 {%0,%1,%2,%3}, [%4];"
                 : "=r"(r[0]), "=r"(r[1]), "=r"(r[2]), "=r"(r[3]) : "r"(addr));
}
__device__ __forceinline__ void mma_bf16(float* c, const uint32_t* a,
                                         uint32_t b0, uint32_t b1) {
    asm volatile("mma.sync.aligned.m16n8k16.row.col.f32.bf16.bf16.f32 "
                 "{%0,%1,%2,%3},{%4,%5,%6,%7},{%8,%9},{%0,%1,%2,%3};"
                 : "+f"(c[0]), "+f"(c[1]), "+f"(c[2]), "+f"(c[3])
                 : "r"(a[0]), "r"(a[1]), "r"(a[2]), "r"(a[3]), "r"(b0), "r"(b1));
}
__device__ __forceinline__ void cp_async16(uint32_t saddr, const void* g) {
    asm volatile("cp.async.ca.shared.global [%0], [%1], 16;"
                 :: "r"(saddr), "l"(g) : "memory");
}
#define CP_COMMIT() asm volatile("cp.async.commit_group;" ::: "memory")
#define CP_WAIT0()  asm volatile("cp.async.wait_group 0;" ::: "memory")

// smem layout
#define SM_AHI 0
#define SM_ALO (SM_AHI + 64 * PITCH_B)        // 17408
#define SM_W0H (SM_ALO + 64 * PITCH_B)        // 34816
#define SM_W0L (SM_W0H + 128 * PITCH_B)       // 69632
#define SM_TOT_P (SM_W0L + 128 * PITCH_B)     // 104448 (dense)
#define SM_W1H SM_TOT_P                        // 104448
#define SM_W1L (SM_W1H + 128 * PITCH_B)       // 139264
#define SM_TOT_F (SM_W1L + 128 * PITCH_B)     // 174080 (fused)

// ---- per-tile building blocks --------------------------------------------
#define LOAD_A_SPLIT(vh, vl, AH, AL, tile)                                     \
    {                                                                          \
        if ((tile) < ntiles) {                                                 \
            size_t bo = (size_t)(tile) * TILE_A_BYTES                          \
                        + (tid >> 2) * PITCH_B + (tid & 3) * 64;               \
            const uint4* ph = reinterpret_cast<const uint4*>((AH) + bo);       \
            const uint4* pl = reinterpret_cast<const uint4*>((AL) + bo);       \
            _Pragma("unroll")                                                  \
            for (int q = 0; q < 4; q++) { vh[q] = __ldg(ph + q); vl[q] = __ldg(pl + q); } \
        }                                                                      \
    }

#define STORE_A_SPLIT(vh, vl)                                                  \
    {                                                                          \
        char* dh = smem + SM_AHI + (tid >> 2) * PITCH_B + (tid & 3) * 64;      \
        char* dl = smem + SM_ALO + (tid >> 2) * PITCH_B + (tid & 3) * 64;      \
        _Pragma("unroll")                                                      \
        for (int q = 0; q < 4; q++) {                                          \
            reinterpret_cast<uint4*>(dh)[q] = vh[q];                           \
            reinterpret_cast<uint4*>(dl)[q] = vl[q];                           \
        }                                                                      \
    }

#define LOAD_A_REGS(v, Aptr, tile)                                             \
    {                                                                          \
        int gm = (tile) * 64 + (tid >> 2);                                     \
        if ((tile) < ntiles && gm < M) {                                       \
            const float4* ap = reinterpret_cast<const float4*>(Aptr)           \
                               + (size_t)gm * 32 + (tid & 3) * 8;              \
            _Pragma("unroll")                                                  \
            for (int q = 0; q < 8; q++) {                                      \
                float4 f = __ldg(ap + q);                                      \
                v[4 * q] = f.x; v[4 * q + 1] = f.y;                            \
                v[4 * q + 2] = f.z; v[4 * q + 3] = f.w;                        \
            }                                                                  \
        } else {                                                               \
            _Pragma("unroll")                                                  \
            for (int q = 0; q < 32; q++) v[q] = 0.f;                           \
        }                                                                      \
    }

#define STORE_CONVERT(v)                                                       \
    {                                                                          \
        uint32_t hp[16], lp[16];                                               \
        _Pragma("unroll")                                                      \
        for (int q = 0; q < 16; q++) split2(v[2 * q], v[2 * q + 1], hp[q], lp[q]); \
        char* dst_h = smem + SM_AHI + (tid >> 2) * PITCH_B + (tid & 3) * 64;   \
        char* dst_l = smem + SM_ALO + (tid >> 2) * PITCH_B + (tid & 3) * 64;   \
        _Pragma("unroll")                                                      \
        for (int q = 0; q < 4; q++) {                                          \
            *reinterpret_cast<uint4*>(dst_h + 16 * q) =                        \
                make_uint4(hp[4 * q], hp[4 * q + 1], hp[4 * q + 2], hp[4 * q + 3]); \
            *reinterpret_cast<uint4*>(dst_l + 16 * q) =                        \
                make_uint4(lp[4 * q], lp[4 * q + 1], lp[4 * q + 2], lp[4 * q + 3]); \
        }                                                                      \
    }

#define ZERO_C()                                                               \
    _Pragma("unroll")                                                          \
    for (int mf = 0; mf < 2; mf++)                                             \
        _Pragma("unroll")                                                      \
        for (int nt = 0; nt < 4; nt++)                                         \
            _Pragma("unroll")                                                  \
            for (int i = 0; i < 4; i++) c[mf][nt][i] = 0.f;

#define MAINLOOP(WHB, WLB)                                                     \
    _Pragma("unroll")                                                          \
    for (int kt = 0; kt < 8; kt++) {                                           \
        const uint32_t kb = kt * 32;                                           \
        uint32_t ah[2][4], al[2][4];                                           \
        ldm_x4(ah[0], sb + SM_AHI + aoff + kb);                                \
        ldm_x4(ah[1], sb + SM_AHI + aoff + 16 * PITCH_B + kb);                 \
        ldm_x4(al[0], sb + SM_ALO + aoff + kb);                                \
        ldm_x4(al[1], sb + SM_ALO + aoff + 16 * PITCH_B + kb);                 \
        uint32_t bh[8], bl[8];                                                 \
        ldm_x4(&bh[0], sb + (WHB) + boff + kb);                                \
        ldm_x4(&bh[4], sb + (WHB) + boff + 16 * PITCH_B + kb);                 \
        ldm_x4(&bl[0], sb + (WLB) + boff + kb);                                \
        ldm_x4(&bl[4], sb + (WLB) + boff + 16 * PITCH_B + kb);                 \
        _Pragma("unroll")                                                      \
        for (int nt = 0; nt < 4; nt++) {                                       \
            uint32_t b0h = bh[2 * nt], b1h = bh[2 * nt + 1];                   \
            uint32_t b0l = bl[2 * nt], b1l = bl[2 * nt + 1];                   \
            _Pragma("unroll")                                                  \
            for (int mf = 0; mf < 2; mf++) {                                   \
                mma_bf16(c[mf][nt], ah[mf], b0h, b1h);                         \
                mma_bf16(c[mf][nt], al[mf], b0h, b1h);                         \
                mma_bf16(c[mf][nt], ah[mf], b0l, b1l);                         \
            }                                                                  \
        }                                                                      \
    }

#define STAGE_W(WHB, WLB, whg, wlg)                                            \
    _Pragma("unroll")                                                          \
    for (int i = tid; i < 2176; i += 256) {                                    \
        cp_async16(sb + (WHB) + i * 16, (const char*)(whg) + i * 16);          \
        cp_async16(sb + (WLB) + i * 16, (const char*)(wlg) + i * 16);          \
    }

// ---------------------------------------------------------------------------
// Persistent dense GEMM, no bias/relu: Y = A @ W^T  (A dense f32, M=40K).
// ---------------------------------------------------------------------------
__global__ void __launch_bounds__(256) gemm_dense_kernel(
    const float* __restrict__ A0,
    const __nv_bfloat16* __restrict__ Wh0, const __nv_bfloat16* __restrict__ Wl0,
    int M, float* __restrict__ Out)
{
    extern __shared__ char smem[];
    const uint32_t sb = smem_u32(smem);
    const int tid = threadIdx.x;
    const int lane = tid & 31;
    const int warp = tid >> 5;
    const int wm = warp & 1;
    const int wn = warp >> 1;
    const int ntiles = (M + 63) / 64;

    const int rA = (lane & 7) + ((lane >> 3) & 1) * 8;
    const int kA = ((lane >> 4) & 1) * 8;
    const int rB = (lane & 7) + ((lane >> 4) & 1) * 8;
    const int kB = ((lane >> 3) & 1) * 8;
    const uint32_t aoff = (uint32_t)((wm * 32 + rA) * PITCH_B + kA * 2);
    const uint32_t boff = (uint32_t)((wn * 32 + rB) * PITCH_B + kB * 2);

    STAGE_W(SM_W0H, SM_W0L, Wh0, Wl0);
    CP_COMMIT();

    float v[32];
    LOAD_A_REGS(v, A0, (int)blockIdx.x);
    CP_WAIT0();

    for (int t = blockIdx.x; t < ntiles; t += gridDim.x) {
        __syncthreads();
        STORE_CONVERT(v);
        __syncthreads();
        LOAD_A_REGS(v, A0, t + (int)gridDim.x);   // prefetch next tile

        float c[2][4][4];
        ZERO_C();
        MAINLOOP(SM_W0H, SM_W0L);

        const int m_base = t * 64;
        #pragma unroll
        for (int nt = 0; nt < 4; nt++) {
            int col = wn * 32 + nt * 8 + 2 * (lane & 3);
            #pragma unroll
            for (int mf = 0; mf < 2; mf++) {
                int row0 = m_base + wm * 32 + mf * 16 + (lane >> 2);
                float2 o01 = make_float2(c[mf][nt][0], c[mf][nt][1]);
                float2 o23 = make_float2(c[mf][nt][2], c[mf][nt][3]);
                if (row0 < M)
                    *reinterpret_cast<float2*>(&Out[(size_t)row0 * D + col]) = o01;
                if (row0 + 8 < M)
                    *reinterpret_cast<float2*>(&Out[(size_t)(row0 + 8) * D + col]) = o23;
            }
        }
    }
}

// ---------------------------------------------------------------------------
// Persistent fused GEMM: Out = relu(A0@W0^T + b0) + A1@W1^T + b1.
// Phase 0: pre-split A (g1 output). Phase 1: dense f32 efeat (convert).
// ---------------------------------------------------------------------------
__global__ void __launch_bounds__(256) gemm_fused_kernel(
    const char* __restrict__ AH, const char* __restrict__ AL,
    const float* __restrict__ bias0,
    const __nv_bfloat16* __restrict__ Wh0, const __nv_bfloat16* __restrict__ Wl0,
    const float* __restrict__ A1, const float* __restrict__ bias1,
    const __nv_bfloat16* __restrict__ Wh1, const __nv_bfloat16* __restrict__ Wl1,
    int M, float* __restrict__ Out)
{
    extern __shared__ char smem[];
    const uint32_t sb = smem_u32(smem);
    const int tid = threadIdx.x;
    const int lane = tid & 31;
    const int warp = tid >> 5;
    const int wm = warp & 1;
    const int wn = warp >> 1;
    const int ntiles = (M + 63) / 64;

    const int rA = (lane & 7) + ((lane >> 3) & 1) * 8;
    const int kA = ((lane >> 4) & 1) * 8;
    const int rB = (lane & 7) + ((lane >> 4) & 1) * 8;
    const int kB = ((lane >> 3) & 1) * 8;
    const uint32_t aoff = (uint32_t)((wm * 32 + rA) * PITCH_B + kA * 2);
    const uint32_t boff = (uint32_t)((wn * 32 + rB) * PITCH_B + kB * 2);

    STAGE_W(SM_W0H, SM_W0L, Wh0, Wl0);
    STAGE_W(SM_W1H, SM_W1L, Wh1, Wl1);
    CP_COMMIT();

    uint4 vh[4], vl[4];
    float v1[32];
    LOAD_A_SPLIT(vh, vl, AH, AL, (int)blockIdx.x);
    CP_WAIT0();

    for (int t = blockIdx.x; t < ntiles; t += gridDim.x) {
        __syncthreads();
        STORE_A_SPLIT(vh, vl);
        __syncthreads();
        LOAD_A_REGS(v1, A1, t);             // phase-1 A prefetch under mainloop0

        float c[2][4][4];
        ZERO_C();
        MAINLOOP(SM_W0H, SM_W0L);

        // mid-fusion: relu(C + bias0)
        #pragma unroll
        for (int nt = 0; nt < 4; nt++) {
            int col = wn * 32 + nt * 8 + 2 * (lane & 3);
            float2 b = __ldg(reinterpret_cast<const float2*>(&bias0[col]));
            #pragma unroll
            for (int mf = 0; mf < 2; mf++) {
                c[mf][nt][0] = fmaxf(c[mf][nt][0] + b.x, 0.f);
                c[mf][nt][1] = fmaxf(c[mf][nt][1] + b.y, 0.f);
                c[mf][nt][2] = fmaxf(c[mf][nt][2] + b.x, 0.f);
                c[mf][nt][3] = fmaxf(c[mf][nt][3] + b.y, 0.f);
            }
        }

        __syncthreads();
        STORE_CONVERT(v1);
        __syncthreads();
        LOAD_A_SPLIT(vh, vl, AH, AL, t + (int)gridDim.x);  // next-tile prefetch

        MAINLOOP(SM_W1H, SM_W1L);

        const int m_base = t * 64;
        #pragma unroll
        for (int nt = 0; nt < 4; nt++) {
            int col = wn * 32 + nt * 8 + 2 * (lane & 3);
            float2 b = __ldg(reinterpret_cast<const float2*>(&bias1[col]));
            #pragma unroll
            for (int mf = 0; mf < 2; mf++) {
                int row0 = m_base + wm * 32 + mf * 16 + (lane >> 2);
                float2 o01 = make_float2(c[mf][nt][0] + b.x, c[mf][nt][1] + b.y);
                float2 o23 = make_float2(c[mf][nt][2] + b.x, c[mf][nt][3] + b.y);
                if (row0 < M)
                    *reinterpret_cast<float2*>(&Out[(size_t)row0 * D + col]) = o01;
                if (row0 + 8 < M)
                    *reinterpret_cast<float2*>(&Out[(size_t)(row0 + 8) * D + col]) = o23;
            }
        }
    }
}

extern "C" void kernel_launch(void* const* d_in, const int* in_sizes, int n_in,
                              void* d_out, int out_size) {
    (void)in_sizes; (void)n_in; (void)out_size;

    const float* vfeat = (const float*)d_in[0];
    const float* efeat = (const float*)d_in[1];
    const float* v_reg_weight = (const float*)d_in[2];
    const float* v_reg_sum    = (const float*)d_in[3];
    const float* e_reg_weight = (const float*)d_in[4];
    const float* e_reg_sum    = (const float*)d_in[5];
    const float* W_ve = (const float*)d_in[6];
    const float* b_ve = (const float*)d_in[7];
    const float* W_ev = (const float*)d_in[8];
    const float* b_ev = (const float*)d_in[9];
    const float* W_ef = (const float*)d_in[10];
    const float* b_ef = (const float*)d_in[11];
    const int* node_idx = (const int*)d_in[12];
    const int* edge_idx = (const int*)d_in[13];

    float* out = (float*)d_out;
    float* vfeat_out = out;
    float* efeat_out = out + (size_t)N_NODES * D;

    __nv_bfloat16 *wh_ptr, *wl_ptr;
    int *offF_e_ptr, *offF_v_ptr, *srt_e_ptr, *srt_v_ptr;
    char *ahe, *ale;
    float* y_ptr;
    cudaGetSymbolAddress((void**)&wh_ptr, g_Wh);
    cudaGetSymbolAddress((void**)&wl_ptr, g_Wl);
    cudaGetSymbolAddress((void**)&offF_e_ptr, g_offF_e);
    cudaGetSymbolAddress((void**)&offF_v_ptr, g_offF_v);
    cudaGetSymbolAddress((void**)&srt_e_ptr, g_srt_e);
    cudaGetSymbolAddress((void**)&srt_v_ptr, g_srt_v);
    cudaGetSymbolAddress((void**)&ahe, g_AHe);
    cudaGetSymbolAddress((void**)&ale, g_ALe);
    cudaGetSymbolAddress((void**)&y_ptr, g_Y);

    cudaFuncSetAttribute(gemm_fused_kernel,
                         cudaFuncAttributeMaxDynamicSharedMemorySize, SM_TOT_F);
    cudaFuncSetAttribute(gemm_dense_kernel,
                         cudaFuncAttributeMaxDynamicSharedMemorySize, SM_TOT_P);

    const size_t WSZ = (size_t)D * W_ROW_U16;

    // --- CSR build + weight split (3 launches) ---
    hist_wsplit_kernel<<<HIST_BLOCKS + WSPLIT_BLOCKS, 256>>>(
        node_idx, edge_idx, W_ve, W_ef, W_ev);
    scan_phaseA2<<<NB_E + NB_V, 512>>>();
    finalize_fill_kernel<<<FINAL_BLOCKS + HIST_BLOCKS, 256>>>(node_idx, edge_idx);

    // --- g1: gather nodes -> edges (pre-split output) ---
    gather_kernel<<<(N_HEDGES * 16 + 255) / 256, 256>>>(
        vfeat, v_reg_weight, e_reg_sum, offF_e_ptr, srt_e_ptr, N_HEDGES, ahe, ale);

    // efeat_out = relu(norm_v @ W_ve^T + b_ve) + efeat @ W_ef^T + b_ef
    gemm_fused_kernel<<<NCTA_FUSED, 256, SM_TOT_F>>>(
        ahe, ale, b_ve, wh_ptr + 0 * WSZ, wl_ptr + 0 * WSZ,
        efeat, b_ef, wh_ptr + 1 * WSZ, wl_ptr + 1 * WSZ,
        N_HEDGES, efeat_out);

    // --- Y = efeat_out @ W_ev^T  (commuted stage-2 GEMM, M=40K) ---
    gemm_dense_kernel<<<NCTA_PLAIN, 256, SM_TOT_P>>>(
        efeat_out, wh_ptr + 2 * WSZ, wl_ptr + 2 * WSZ, N_HEDGES, y_ptr);

    // --- vfeat_out = relu(gather_v(Y)/v_reg_sum + b_ev) ---
    gather_final_kernel<<<(N_NODES * 16 + 255) / 256, 256>>>(
        y_ptr, e_reg_weight, v_reg_sum, offF_v_ptr, srt_v_ptr, N_NODES,
        b_ev, vfeat_out);
}